// round 13
// baseline (speedup 1.0000x reference)
#include <cuda_runtime.h>
#include <cuda_fp16.h>
#include <math.h>
#include <stdint.h>

#define N_TOKENS 16384
#define D_MODEL  1024
#define D_FF     2048
#define N_EXPERTS 4

// ---------------- scratch (device globals; no allocation allowed) ----------------
__device__ int    g_cnt[N_EXPERTS];
__device__ int    g_tok[N_EXPERTS * N_TOKENS];
__device__ int    g_eidx[2 * N_TOKENS];
__device__ int    g_slot[2 * N_TOKENS];
__device__ float  g_wsm [2 * N_TOKENS];
__device__ __half g_Xh [(size_t)N_TOKENS * D_MODEL];
__device__ __half g_W1h[(size_t)N_EXPERTS * D_FF * D_MODEL];
__device__ __half g_W2h[(size_t)N_EXPERTS * D_MODEL * D_FF];
__device__ __half g_Hh [(size_t)N_EXPERTS * N_TOKENS * D_FF];
__device__ float  g_Z  [(size_t)N_EXPERTS * N_TOKENS * D_MODEL];

__device__ __forceinline__ float gelu_exact(float v) {
    return 0.5f * v * (1.0f + erff(v * 0.70710678118654752440f));
}

__device__ __forceinline__ void mma_f16(float c[4], const uint32_t a[4], const uint32_t b[2]) {
    asm volatile(
        "mma.sync.aligned.m16n8k16.row.col.f32.f16.f16.f32 "
        "{%0,%1,%2,%3}, {%4,%5,%6,%7}, {%8,%9}, {%0,%1,%2,%3};"
        : "+f"(c[0]), "+f"(c[1]), "+f"(c[2]), "+f"(c[3])
        : "r"(a[0]), "r"(a[1]), "r"(a[2]), "r"(a[3]), "r"(b[0]), "r"(b[1]));
}

#define LDSM_X4(r0, r1, r2, r3, addr) \
    asm volatile("ldmatrix.sync.aligned.m8n8.x4.shared.b16 {%0,%1,%2,%3}, [%4];" \
                 : "=r"(r0), "=r"(r1), "=r"(r2), "=r"(r3) : "r"(addr))

__device__ __forceinline__ uint32_t smem_u32(const void* p) {
    uint32_t a;
    asm("{ .reg .u64 t; cvta.to.shared.u64 t, %1; cvt.u32.u64 %0, t; }" : "=r"(a) : "l"(p));
    return a;
}
__device__ __forceinline__ void cpasync16(uint32_t dst, const void* src) {
    asm volatile("cp.async.cg.shared.global [%0], [%1], 16;" :: "r"(dst), "l"(src));
}
__device__ __forceinline__ void cp_commit() {
    asm volatile("cp.async.commit_group;" ::: "memory");
}
__device__ __forceinline__ void cp_wait3() {
    asm volatile("cp.async.wait_group 3;" ::: "memory");
}
__device__ __forceinline__ void cp_wait0() {
    asm volatile("cp.async.wait_group 0;" ::: "memory");
}

// ---------------- init ----------------
__global__ void init_counts_kernel() {
    if (threadIdx.x < N_EXPERTS) g_cnt[threadIdx.x] = 0;
}

// ---------------- fp32 -> fp16 conversion (vectorized) ----------------
__global__ void __launch_bounds__(256) f2h_kernel(const float4* __restrict__ src,
                                                  __half2* __restrict__ dst, int n4) {
    int i = blockIdx.x * 256 + threadIdx.x;
    if (i < n4) {
        float4 v = src[i];
        dst[2 * i + 0] = __floats2half2_rn(v.x, v.y);
        dst[2 * i + 1] = __floats2half2_rn(v.z, v.w);
    }
}

// ---------------- gating: scores, top-2, softmax, compaction; fused x->fp16 ----------------
__global__ void __launch_bounds__(256) gate_kernel(const float* __restrict__ x,
                                                   const float* __restrict__ gate_w) {
    __shared__ float sgw[N_EXPERTS * D_MODEL];
    const int tid = threadIdx.x;
    for (int i = tid; i < N_EXPERTS * D_MODEL; i += 256) sgw[i] = gate_w[i];
    __syncthreads();

    const int warp = tid >> 5, lane = tid & 31;
    const int tok = blockIdx.x * 8 + warp;
    if (tok >= N_TOKENS) return;

    const float4* xr4 = (const float4*)(x + (size_t)tok * D_MODEL);
    __half2* xh2 = (__half2*)(g_Xh + (size_t)tok * D_MODEL);

    float acc0 = 0.f, acc1 = 0.f, acc2 = 0.f, acc3 = 0.f;
    #pragma unroll
    for (int j = 0; j < 8; j++) {
        const int i4 = lane + 32 * j;        // float4 index within row (0..255)
        float4 v = xr4[i4];
        // fused fp16 conversion store
        xh2[2 * i4 + 0] = __floats2half2_rn(v.x, v.y);
        xh2[2 * i4 + 1] = __floats2half2_rn(v.z, v.w);
        const int k = i4 * 4;
        acc0 += v.x * sgw[0 * D_MODEL + k] + v.y * sgw[0 * D_MODEL + k + 1]
              + v.z * sgw[0 * D_MODEL + k + 2] + v.w * sgw[0 * D_MODEL + k + 3];
        acc1 += v.x * sgw[1 * D_MODEL + k] + v.y * sgw[1 * D_MODEL + k + 1]
              + v.z * sgw[1 * D_MODEL + k + 2] + v.w * sgw[1 * D_MODEL + k + 3];
        acc2 += v.x * sgw[2 * D_MODEL + k] + v.y * sgw[2 * D_MODEL + k + 1]
              + v.z * sgw[2 * D_MODEL + k + 2] + v.w * sgw[2 * D_MODEL + k + 3];
        acc3 += v.x * sgw[3 * D_MODEL + k] + v.y * sgw[3 * D_MODEL + k + 1]
              + v.z * sgw[3 * D_MODEL + k + 2] + v.w * sgw[3 * D_MODEL + k + 3];
    }
    #pragma unroll
    for (int o = 16; o; o >>= 1) {
        acc0 += __shfl_xor_sync(0xffffffffu, acc0, o);
        acc1 += __shfl_xor_sync(0xffffffffu, acc1, o);
        acc2 += __shfl_xor_sync(0xffffffffu, acc2, o);
        acc3 += __shfl_xor_sync(0xffffffffu, acc3, o);
    }
    if (lane == 0) {
        float s[4] = {acc0, acc1, acc2, acc3};
        int i0 = 0;
        #pragma unroll
        for (int e = 1; e < 4; e++) if (s[e] > s[i0]) i0 = e;
        int i1 = -1;
        #pragma unroll
        for (int e = 0; e < 4; e++) {
            if (e == i0) continue;
            if (i1 < 0 || s[e] > s[i1]) i1 = e;
        }
        float t  = expf(s[i1] - s[i0]);
        float p0 = 1.0f / (1.0f + t);
        float p1 = t / (1.0f + t);

        int sl0 = atomicAdd(&g_cnt[i0], 1);
        g_tok[i0 * N_TOKENS + sl0] = tok;
        int sl1 = atomicAdd(&g_cnt[i1], 1);
        g_tok[i1 * N_TOKENS + sl1] = tok;

        g_eidx[2 * tok + 0] = i0;  g_slot[2 * tok + 0] = sl0;  g_wsm[2 * tok + 0] = p0;
        g_eidx[2 * tok + 1] = i1;  g_slot[2 * tok + 1] = sl1;  g_wsm[2 * tok + 1] = p1;
    }
}

// ======================= FP16 tensor-core GEMMs (m16n8k16 + ldmatrix) =======================
// CTA 128(M) x 256(N), 512 threads = 16 warps (2 M x 8 N), warp tile 64x32.
// BK=32 halves, 5-stage cp.async pipeline (wait3), SROW=40 halves.
#define BK 32
#define SROW 40
#define STAGES 5
#define BN 256
#define A_STAGE_H (128 * SROW)                   // 5120 halves
#define A_STAGE_B (A_STAGE_H * 2)                // 10240 bytes
#define B_STAGE_H (BN * SROW)                    // 10240 halves
#define STAGE_H   (A_STAGE_H + B_STAGE_H)        // 15360 halves
#define STAGE_B   (STAGE_H * 2)                  // 30720 bytes
#define SMEM_DYN  (STAGES * STAGE_B)             // 153600 bytes

template<int KDIM, bool G1>
__global__ void __launch_bounds__(512, 1) moe_gemm(
    const __half* __restrict__ Asrc, const __half* __restrict__ Wh,
    const float* __restrict__ bias, const float* __restrict__ resid)
{
    const int e   = blockIdx.z;
    const int cnt = g_cnt[e];
    const int m0  = blockIdx.y * 128;
    if (m0 >= cnt) return;
    const int n0  = blockIdx.x * BN;

    extern __shared__ __half smem[];
    __shared__ int stok[128];

    const int tid = threadIdx.x;
    if (tid < 128) {
        int m = m0 + tid;
        stok[tid] = g_tok[e * N_TOKENS + (m < cnt ? m : cnt - 1)];
    }
    __syncthreads();

    // ---- loader mapping: thread t -> A row t>>2 quad t&3; B rows t>>2 and 128+(t>>2) ----
    const int lrow = tid >> 2;       // 0..127
    const int quad = tid & 3;        // 16B chunk within 32-half row

    const __half* aptr;
    if (G1) {
        aptr = Asrc + (size_t)stok[lrow] * KDIM + quad * 8;
    } else {
        int mr = m0 + lrow; if (mr >= cnt) mr = cnt - 1;
        aptr = Asrc + ((size_t)e * N_TOKENS + mr) * KDIM + quad * 8;
    }
    const __half* wbase = Wh + (size_t)e * ((size_t)D_FF * D_MODEL);
    const __half* bptr0 = wbase + (size_t)(n0 + lrow)       * KDIM + quad * 8;
    const __half* bptr1 = wbase + (size_t)(n0 + 128 + lrow) * KDIM + quad * 8;

    const uint32_t sbase = smem_u32(smem);
    const uint32_t aoff  = (uint32_t)(lrow * SROW + quad * 8) * 2u;
    const uint32_t boff0 = (uint32_t)A_STAGE_B + aoff;
    const uint32_t boff1 = boff0 + (uint32_t)(128 * SROW * 2);

    auto issue = [&](int t, int s) {
        const int kt = t * BK;
        const uint32_t sa = sbase + (uint32_t)s * STAGE_B;
        cpasync16(sa + aoff,  aptr  + kt);
        cpasync16(sa + boff0, bptr0 + kt);
        cpasync16(sa + boff1, bptr1 + kt);
    };

    // ---- compute mapping: 16 warps = 2 (M) x 8 (N), warp tile 64x32 ----
    const int warp = tid >> 5, lane = tid & 31;
    const int wm = (warp & 1) * 64;
    const int wn = (warp >> 1) * 32;
    const int gid = lane >> 2, tig = lane & 3;

    uint32_t a_lm[4];
    #pragma unroll
    for (int mt = 0; mt < 4; mt++)
        a_lm[mt] = (uint32_t)((wm + mt * 16 + (lane & 15)) * SROW + ((lane >> 4) * 8)) * 2u;
    const uint32_t b_lm = (uint32_t)((wn + lane) * SROW) * 2u + (uint32_t)A_STAGE_B;

    float acc[4][4][4];
    #pragma unroll
    for (int mt = 0; mt < 4; mt++)
        #pragma unroll
        for (int nt = 0; nt < 4; nt++)
            #pragma unroll
            for (int r = 0; r < 4; r++) acc[mt][nt][r] = 0.f;

    constexpr int T = KDIM / BK;

    issue(0, 0); cp_commit();
    issue(1, 1); cp_commit();
    issue(2, 2); cp_commit();
    issue(3, 3); cp_commit();

    for (int t = 0; t < T; t++) {
        const int s = t % STAGES;
        if (t + 4 < T) cp_wait3(); else cp_wait0();
        __syncthreads();
        if (t + 4 < T) { issue(t + 4, (t + 4) % STAGES); cp_commit(); }

        const uint32_t sa = sbase + (uint32_t)s * STAGE_B;

        #pragma unroll
        for (int ks = 0; ks < 2; ks++) {
            const uint32_t kb = (uint32_t)(ks * 16 * 2);   // byte offset of 16-col block
            uint32_t af[4][4], bf[4][2];
            #pragma unroll
            for (int mt = 0; mt < 4; mt++)
                LDSM_X4(af[mt][0], af[mt][1], af[mt][2], af[mt][3], sa + a_lm[mt] + kb);
            {
                uint32_t r0, r1, r2, r3;
                LDSM_X4(r0, r1, r2, r3, sa + b_lm + kb);
                bf[0][0] = r0; bf[1][0] = r1; bf[2][0] = r2; bf[3][0] = r3;
                LDSM_X4(r0, r1, r2, r3, sa + b_lm + kb + 16u);
                bf[0][1] = r0; bf[1][1] = r1; bf[2][1] = r2; bf[3][1] = r3;
            }
            #pragma unroll
            for (int mt = 0; mt < 4; mt++)
                #pragma unroll
                for (int nt = 0; nt < 4; nt++)
                    mma_f16(acc[mt][nt], af[mt], bf[nt]);
        }
    }

    // ---- epilogue ----
    #pragma unroll
    for (int nt = 0; nt < 4; nt++) {
        const int nl = wn + nt * 8 + tig * 2;
        if (G1) {
            float2 bb = *(const float2*)(bias + (size_t)e * D_FF + n0 + nl);
            #pragma unroll
            for (int mt = 0; mt < 4; mt++) {
                int mA = m0 + wm + mt * 16 + gid;
                if (mA < cnt) {
                    float vx = gelu_exact(acc[mt][nt][0] + bb.x);
                    float vy = gelu_exact(acc[mt][nt][1] + bb.y);
                    *(__half2*)(g_Hh + ((size_t)e * N_TOKENS + mA) * D_FF + n0 + nl)
                        = __floats2half2_rn(vx, vy);
                }
                int mB = mA + 8;
                if (mB < cnt) {
                    float vx = gelu_exact(acc[mt][nt][2] + bb.x);
                    float vy = gelu_exact(acc[mt][nt][3] + bb.y);
                    *(__half2*)(g_Hh + ((size_t)e * N_TOKENS + mB) * D_FF + n0 + nl)
                        = __floats2half2_rn(vx, vy);
                }
            }
        } else {
            float2 bb = *(const float2*)(bias + (size_t)e * D_MODEL + n0 + nl);
            #pragma unroll
            for (int mt = 0; mt < 4; mt++) {
                int mA = m0 + wm + mt * 16 + gid;
                if (mA < cnt) {
                    int tok = stok[wm + mt * 16 + gid];
                    float2 xv = *(const float2*)(resid + (size_t)tok * D_MODEL + n0 + nl);
                    float2 v;
                    v.x = acc[mt][nt][0] + bb.x + xv.x;
                    v.y = acc[mt][nt][1] + bb.y + xv.y;
                    *(float2*)(g_Z + ((size_t)e * N_TOKENS + mA) * D_MODEL + n0 + nl) = v;
                }
                int mB = mA + 8;
                if (mB < cnt) {
                    int tok = stok[wm + mt * 16 + gid + 8];
                    float2 xv = *(const float2*)(resid + (size_t)tok * D_MODEL + n0 + nl);
                    float2 v;
                    v.x = acc[mt][nt][2] + bb.x + xv.x;
                    v.y = acc[mt][nt][3] + bb.y + xv.y;
                    *(float2*)(g_Z + ((size_t)e * N_TOKENS + mB) * D_MODEL + n0 + nl) = v;
                }
            }
        }
    }
}

// -------- LayerNorm: one block per token, both experts, direct write (no atomics) --------
__global__ void __launch_bounds__(256) ln_kernel(const float* __restrict__ gamma,
                                                 const float* __restrict__ beta,
                                                 float* __restrict__ out) {
    const int tok = blockIdx.x;
    const int tid  = threadIdx.x;
    const int lane = tid & 31, warp = tid >> 5;

    __shared__ float red1[8];
    __shared__ float red2[8];

    float4 osum = make_float4(0.f, 0.f, 0.f, 0.f);

    #pragma unroll
    for (int j = 0; j < 2; j++) {
        const int   e    = g_eidx[2 * tok + j];
        const int   slot = g_slot[2 * tok + j];
        const float w    = g_wsm [2 * tok + j];
        const float* z   = g_Z + ((size_t)e * N_TOKENS + slot) * D_MODEL;

        float4 v = ((const float4*)z)[tid];

        float s = v.x + v.y + v.z + v.w;
        #pragma unroll
        for (int o = 16; o; o >>= 1) s += __shfl_xor_sync(0xffffffffu, s, o);
        if (lane == 0) red1[warp] = s;
        __syncthreads();
        float tot = 0.f;
        #pragma unroll
        for (int i = 0; i < 8; i++) tot += red1[i];
        const float mu = tot * (1.0f / D_MODEL);

        float dx = v.x - mu, dy = v.y - mu, dz = v.z - mu, dw = v.w - mu;
        float sq = dx * dx + dy * dy + dz * dz + dw * dw;
        #pragma unroll
        for (int o = 16; o; o >>= 1) sq += __shfl_xor_sync(0xffffffffu, sq, o);
        if (lane == 0) red2[warp] = sq;
        __syncthreads();
        float tot2 = 0.f;
        #pragma unroll
        for (int i = 0; i < 8; i++) tot2 += red2[i];
        const float var  = tot2 * (1.0f / D_MODEL);
        const float rstd = rsqrtf(var + 1e-6f);

        float4 g  = ((const float4*)(gamma + (size_t)e * D_MODEL))[tid];
        float4 bb = ((const float4*)(beta  + (size_t)e * D_MODEL))[tid];

        osum.x += w * (dx * rstd * g.x + bb.x);
        osum.y += w * (dy * rstd * g.y + bb.y);
        osum.z += w * (dz * rstd * g.z + bb.z);
        osum.w += w * (dw * rstd * g.w + bb.w);
        __syncthreads();
    }

    ((float4*)(out + (size_t)tok * D_MODEL))[tid] = osum;
}

// ---------------- launch ----------------
extern "C" void kernel_launch(void* const* d_in, const int* in_sizes, int n_in,
                              void* d_out, int out_size) {
    const float* x      = (const float*)d_in[0];
    const float* gate_w = (const float*)d_in[1];
    const float* w1     = (const float*)d_in[2];
    const float* b1     = (const float*)d_in[3];
    const float* w2     = (const float*)d_in[4];
    const float* b2     = (const float*)d_in[5];
    const float* gamma  = (const float*)d_in[6];
    const float* beta   = (const float*)d_in[7];

    __half *xh = nullptr, *w1h = nullptr, *w2h = nullptr, *hh = nullptr;
    cudaGetSymbolAddress((void**)&xh,  g_Xh);
    cudaGetSymbolAddress((void**)&w1h, g_W1h);
    cudaGetSymbolAddress((void**)&w2h, g_W2h);
    cudaGetSymbolAddress((void**)&hh,  g_Hh);

    cudaFuncSetAttribute(moe_gemm<D_MODEL, true>,
                         cudaFuncAttributeMaxDynamicSharedMemorySize, SMEM_DYN);
    cudaFuncSetAttribute(moe_gemm<D_FF, false>,
                         cudaFuncAttributeMaxDynamicSharedMemorySize, SMEM_DYN);

    init_counts_kernel<<<1, 32>>>();

    // weight conversions (x conversion fused into gate_kernel)
    {
        int n4 = (N_EXPERTS * D_FF * D_MODEL) / 4;
        f2h_kernel<<<(n4 + 255) / 256, 256>>>((const float4*)w1, (__half2*)w1h, n4);
        f2h_kernel<<<(n4 + 255) / 256, 256>>>((const float4*)w2, (__half2*)w2h, n4);
    }

    gate_kernel<<<N_TOKENS / 8, 256>>>(x, gate_w);

    dim3 g1(D_FF / BN, N_TOKENS / 128, N_EXPERTS);
    moe_gemm<D_MODEL, true><<<g1, 512, SMEM_DYN>>>(xh, w1h, b1, nullptr);

    dim3 g2(D_MODEL / BN, N_TOKENS / 128, N_EXPERTS);
    moe_gemm<D_FF, false><<<g2, 512, SMEM_DYN>>>(hh, w2h, b2, x);

    ln_kernel<<<N_TOKENS, 256>>>(gamma, beta, (float*)d_out);
}

// round 14
// speedup vs baseline: 1.5926x; 1.5926x over previous
#include <cuda_runtime.h>
#include <cuda_fp16.h>
#include <math.h>
#include <stdint.h>

#define N_TOKENS 16384
#define D_MODEL  1024
#define D_FF     2048
#define N_EXPERTS 4

// ---------------- scratch (device globals; no allocation allowed) ----------------
__device__ int    g_cnt[N_EXPERTS];
__device__ int    g_tok[N_EXPERTS * N_TOKENS];
__device__ int    g_eidx[2 * N_TOKENS];
__device__ int    g_slot[2 * N_TOKENS];
__device__ float  g_wsm [2 * N_TOKENS];
__device__ __half g_Xh [(size_t)N_TOKENS * D_MODEL];
__device__ __half g_W1h[(size_t)N_EXPERTS * D_FF * D_MODEL];
__device__ __half g_W2h[(size_t)N_EXPERTS * D_MODEL * D_FF];
__device__ __half g_Hh [(size_t)N_EXPERTS * N_TOKENS * D_FF];
__device__ float  g_Z  [(size_t)N_EXPERTS * N_TOKENS * D_MODEL];

__device__ __forceinline__ float gelu_exact(float v) {
    return 0.5f * v * (1.0f + erff(v * 0.70710678118654752440f));
}

__device__ __forceinline__ void mma_f16(float c[4], const uint32_t a[4], const uint32_t b[2]) {
    asm volatile(
        "mma.sync.aligned.m16n8k16.row.col.f32.f16.f16.f32 "
        "{%0,%1,%2,%3}, {%4,%5,%6,%7}, {%8,%9}, {%0,%1,%2,%3};"
        : "+f"(c[0]), "+f"(c[1]), "+f"(c[2]), "+f"(c[3])
        : "r"(a[0]), "r"(a[1]), "r"(a[2]), "r"(a[3]), "r"(b[0]), "r"(b[1]));
}

#define LDSM_X4(r0, r1, r2, r3, addr) \
    asm volatile("ldmatrix.sync.aligned.m8n8.x4.shared.b16 {%0,%1,%2,%3}, [%4];" \
                 : "=r"(r0), "=r"(r1), "=r"(r2), "=r"(r3) : "r"(addr))

__device__ __forceinline__ uint32_t smem_u32(const void* p) {
    uint32_t a;
    asm("{ .reg .u64 t; cvta.to.shared.u64 t, %1; cvt.u32.u64 %0, t; }" : "=r"(a) : "l"(p));
    return a;
}
__device__ __forceinline__ void cpasync16(uint32_t dst, const void* src) {
    asm volatile("cp.async.cg.shared.global [%0], [%1], 16;" :: "r"(dst), "l"(src));
}
__device__ __forceinline__ void cp_commit() {
    asm volatile("cp.async.commit_group;" ::: "memory");
}
__device__ __forceinline__ void cp_wait2() {
    asm volatile("cp.async.wait_group 2;" ::: "memory");
}
__device__ __forceinline__ void cp_wait0() {
    asm volatile("cp.async.wait_group 0;" ::: "memory");
}

// ---------------- init ----------------
__global__ void init_counts_kernel() {
    if (threadIdx.x < N_EXPERTS) g_cnt[threadIdx.x] = 0;
}

// ---------------- fp32 -> fp16 conversion (vectorized) ----------------
__global__ void __launch_bounds__(256) f2h_kernel(const float4* __restrict__ src,
                                                  __half2* __restrict__ dst, int n4) {
    int i = blockIdx.x * 256 + threadIdx.x;
    if (i < n4) {
        float4 v = src[i];
        dst[2 * i + 0] = __floats2half2_rn(v.x, v.y);
        dst[2 * i + 1] = __floats2half2_rn(v.z, v.w);
    }
}

// ---------------- gating: scores, top-2, softmax, compaction ----------------
__global__ void __launch_bounds__(256) gate_kernel(const float* __restrict__ x,
                                                   const float* __restrict__ gate_w) {
    __shared__ float sgw[N_EXPERTS * D_MODEL];
    const int tid = threadIdx.x;
    for (int i = tid; i < N_EXPERTS * D_MODEL; i += 256) sgw[i] = gate_w[i];
    __syncthreads();

    const int warp = tid >> 5, lane = tid & 31;
    const int tok = blockIdx.x * 8 + warp;
    if (tok >= N_TOKENS) return;

    const float* xr = x + (size_t)tok * D_MODEL;
    float acc0 = 0.f, acc1 = 0.f, acc2 = 0.f, acc3 = 0.f;
    for (int k = lane; k < D_MODEL; k += 32) {
        float xv = xr[k];
        acc0 += xv * sgw[0 * D_MODEL + k];
        acc1 += xv * sgw[1 * D_MODEL + k];
        acc2 += xv * sgw[2 * D_MODEL + k];
        acc3 += xv * sgw[3 * D_MODEL + k];
    }
    #pragma unroll
    for (int o = 16; o; o >>= 1) {
        acc0 += __shfl_xor_sync(0xffffffffu, acc0, o);
        acc1 += __shfl_xor_sync(0xffffffffu, acc1, o);
        acc2 += __shfl_xor_sync(0xffffffffu, acc2, o);
        acc3 += __shfl_xor_sync(0xffffffffu, acc3, o);
    }
    if (lane == 0) {
        float s[4] = {acc0, acc1, acc2, acc3};
        int i0 = 0;
        #pragma unroll
        for (int e = 1; e < 4; e++) if (s[e] > s[i0]) i0 = e;
        int i1 = -1;
        #pragma unroll
        for (int e = 0; e < 4; e++) {
            if (e == i0) continue;
            if (i1 < 0 || s[e] > s[i1]) i1 = e;
        }
        float t  = expf(s[i1] - s[i0]);
        float p0 = 1.0f / (1.0f + t);
        float p1 = t / (1.0f + t);

        int sl0 = atomicAdd(&g_cnt[i0], 1);
        g_tok[i0 * N_TOKENS + sl0] = tok;
        int sl1 = atomicAdd(&g_cnt[i1], 1);
        g_tok[i1 * N_TOKENS + sl1] = tok;

        g_eidx[2 * tok + 0] = i0;  g_slot[2 * tok + 0] = sl0;  g_wsm[2 * tok + 0] = p0;
        g_eidx[2 * tok + 1] = i1;  g_slot[2 * tok + 1] = sl1;  g_wsm[2 * tok + 1] = p1;
    }
}

// ======================= FP16 tensor-core GEMMs (m16n8k16 + ldmatrix) =======================
// CTA 128(M) x 256(N), 512 threads = 16 warps (2 M x 8 N), warp tile 64x32.
// BK=32 halves, 4-stage cp.async pipeline (wait2), SROW=40 halves.
#define BK 32
#define SROW 40
#define STAGES 4
#define BN 256
#define A_STAGE_H (128 * SROW)                   // 5120 halves
#define A_STAGE_B (A_STAGE_H * 2)                // 10240 bytes
#define B_STAGE_H (BN * SROW)                    // 10240 halves
#define STAGE_H   (A_STAGE_H + B_STAGE_H)        // 15360 halves
#define STAGE_B   (STAGE_H * 2)                  // 30720 bytes
#define SMEM_DYN  (STAGES * STAGE_B)             // 122880 bytes

template<int KDIM, bool G1>
__global__ void __launch_bounds__(512, 1) moe_gemm(
    const __half* __restrict__ Asrc, const __half* __restrict__ Wh,
    const float* __restrict__ bias, const float* __restrict__ resid)
{
    const int e   = blockIdx.z;
    const int cnt = g_cnt[e];
    const int m0  = blockIdx.y * 128;
    if (m0 >= cnt) return;
    const int n0  = blockIdx.x * BN;

    extern __shared__ __half smem[];
    __shared__ int stok[128];

    const int tid = threadIdx.x;
    if (tid < 128) {
        int m = m0 + tid;
        stok[tid] = g_tok[e * N_TOKENS + (m < cnt ? m : cnt - 1)];
    }
    __syncthreads();

    // ---- loader mapping: thread t -> A row t>>2 quad t&3; B rows t>>2 and 128+(t>>2) ----
    const int lrow = tid >> 2;       // 0..127
    const int quad = tid & 3;        // 16B chunk within 32-half row

    const __half* aptr;
    if (G1) {
        aptr = Asrc + (size_t)stok[lrow] * KDIM + quad * 8;
    } else {
        int mr = m0 + lrow; if (mr >= cnt) mr = cnt - 1;
        aptr = Asrc + ((size_t)e * N_TOKENS + mr) * KDIM + quad * 8;
    }
    const __half* wbase = Wh + (size_t)e * ((size_t)D_FF * D_MODEL);
    const __half* bptr0 = wbase + (size_t)(n0 + lrow)       * KDIM + quad * 8;
    const __half* bptr1 = wbase + (size_t)(n0 + 128 + lrow) * KDIM + quad * 8;

    const uint32_t sbase = smem_u32(smem);
    const uint32_t aoff  = (uint32_t)(lrow * SROW + quad * 8) * 2u;
    const uint32_t boff0 = (uint32_t)A_STAGE_B + aoff;
    const uint32_t boff1 = boff0 + (uint32_t)(128 * SROW * 2);

    auto issue = [&](int t, int s) {
        const int kt = t * BK;
        const uint32_t sa = sbase + (uint32_t)s * STAGE_B;
        cpasync16(sa + aoff,  aptr  + kt);
        cpasync16(sa + boff0, bptr0 + kt);
        cpasync16(sa + boff1, bptr1 + kt);
    };

    // ---- compute mapping: 16 warps = 2 (M) x 8 (N), warp tile 64x32 ----
    const int warp = tid >> 5, lane = tid & 31;
    const int wm = (warp & 1) * 64;
    const int wn = (warp >> 1) * 32;
    const int gid = lane >> 2, tig = lane & 3;

    uint32_t a_lm[4];
    #pragma unroll
    for (int mt = 0; mt < 4; mt++)
        a_lm[mt] = (uint32_t)((wm + mt * 16 + (lane & 15)) * SROW + ((lane >> 4) * 8)) * 2u;
    const uint32_t b_lm = (uint32_t)((wn + lane) * SROW) * 2u + (uint32_t)A_STAGE_B;

    float acc[4][4][4];
    #pragma unroll
    for (int mt = 0; mt < 4; mt++)
        #pragma unroll
        for (int nt = 0; nt < 4; nt++)
            #pragma unroll
            for (int r = 0; r < 4; r++) acc[mt][nt][r] = 0.f;

    constexpr int T = KDIM / BK;

    issue(0, 0); cp_commit();
    issue(1, 1); cp_commit();
    issue(2, 2); cp_commit();

    for (int t = 0; t < T; t++) {
        const int s = t % STAGES;
        if (t + 3 < T) cp_wait2(); else cp_wait0();
        __syncthreads();
        if (t + 3 < T) { issue(t + 3, (t + 3) % STAGES); cp_commit(); }

        const uint32_t sa = sbase + (uint32_t)s * STAGE_B;

        #pragma unroll
        for (int ks = 0; ks < 2; ks++) {
            const uint32_t kb = (uint32_t)(ks * 16 * 2);   // byte offset of 16-col block
            uint32_t af[4][4], bf[4][2];
            #pragma unroll
            for (int mt = 0; mt < 4; mt++)
                LDSM_X4(af[mt][0], af[mt][1], af[mt][2], af[mt][3], sa + a_lm[mt] + kb);
            {
                uint32_t r0, r1, r2, r3;
                LDSM_X4(r0, r1, r2, r3, sa + b_lm + kb);
                bf[0][0] = r0; bf[1][0] = r1; bf[2][0] = r2; bf[3][0] = r3;
                LDSM_X4(r0, r1, r2, r3, sa + b_lm + kb + 16u);
                bf[0][1] = r0; bf[1][1] = r1; bf[2][1] = r2; bf[3][1] = r3;
            }
            #pragma unroll
            for (int mt = 0; mt < 4; mt++)
                #pragma unroll
                for (int nt = 0; nt < 4; nt++)
                    mma_f16(acc[mt][nt], af[mt], bf[nt]);
        }
    }

    // ---- epilogue ----
    #pragma unroll
    for (int nt = 0; nt < 4; nt++) {
        const int nl = wn + nt * 8 + tig * 2;
        if (G1) {
            float2 bb = *(const float2*)(bias + (size_t)e * D_FF + n0 + nl);
            #pragma unroll
            for (int mt = 0; mt < 4; mt++) {
                int mA = m0 + wm + mt * 16 + gid;
                if (mA < cnt) {
                    float vx = gelu_exact(acc[mt][nt][0] + bb.x);
                    float vy = gelu_exact(acc[mt][nt][1] + bb.y);
                    *(__half2*)(g_Hh + ((size_t)e * N_TOKENS + mA) * D_FF + n0 + nl)
                        = __floats2half2_rn(vx, vy);
                }
                int mB = mA + 8;
                if (mB < cnt) {
                    float vx = gelu_exact(acc[mt][nt][2] + bb.x);
                    float vy = gelu_exact(acc[mt][nt][3] + bb.y);
                    *(__half2*)(g_Hh + ((size_t)e * N_TOKENS + mB) * D_FF + n0 + nl)
                        = __floats2half2_rn(vx, vy);
                }
            }
        } else {
            float2 bb = *(const float2*)(bias + (size_t)e * D_MODEL + n0 + nl);
            #pragma unroll
            for (int mt = 0; mt < 4; mt++) {
                int mA = m0 + wm + mt * 16 + gid;
                if (mA < cnt) {
                    int tok = stok[wm + mt * 16 + gid];
                    float2 xv = *(const float2*)(resid + (size_t)tok * D_MODEL + n0 + nl);
                    float2 v;
                    v.x = acc[mt][nt][0] + bb.x + xv.x;
                    v.y = acc[mt][nt][1] + bb.y + xv.y;
                    *(float2*)(g_Z + ((size_t)e * N_TOKENS + mA) * D_MODEL + n0 + nl) = v;
                }
                int mB = mA + 8;
                if (mB < cnt) {
                    int tok = stok[wm + mt * 16 + gid + 8];
                    float2 xv = *(const float2*)(resid + (size_t)tok * D_MODEL + n0 + nl);
                    float2 v;
                    v.x = acc[mt][nt][2] + bb.x + xv.x;
                    v.y = acc[mt][nt][3] + bb.y + xv.y;
                    *(float2*)(g_Z + ((size_t)e * N_TOKENS + mB) * D_MODEL + n0 + nl) = v;
                }
            }
        }
    }
}

// -------- LayerNorm: one block per token, BOTH experts in one pass, direct write --------
__global__ void __launch_bounds__(256) ln_kernel(const float* __restrict__ gamma,
                                                 const float* __restrict__ beta,
                                                 float* __restrict__ out) {
    const int tok = blockIdx.x;
    const int tid  = threadIdx.x;
    const int lane = tid & 31, warp = tid >> 5;

    __shared__ float redA0[8];
    __shared__ float redA1[8];
    __shared__ float redB0[8];
    __shared__ float redB1[8];

    const int   e0 = g_eidx[2 * tok + 0], e1 = g_eidx[2 * tok + 1];
    const int   sl0 = g_slot[2 * tok + 0], sl1 = g_slot[2 * tok + 1];
    const float w0 = g_wsm[2 * tok + 0], w1 = g_wsm[2 * tok + 1];

    float4 v0 = ((const float4*)(g_Z + ((size_t)e0 * N_TOKENS + sl0) * D_MODEL))[tid];
    float4 v1 = ((const float4*)(g_Z + ((size_t)e1 * N_TOKENS + sl1) * D_MODEL))[tid];

    // pass 1: sums (both experts, one barrier)
    float s0 = v0.x + v0.y + v0.z + v0.w;
    float s1 = v1.x + v1.y + v1.z + v1.w;
    #pragma unroll
    for (int o = 16; o; o >>= 1) {
        s0 += __shfl_xor_sync(0xffffffffu, s0, o);
        s1 += __shfl_xor_sync(0xffffffffu, s1, o);
    }
    if (lane == 0) { redA0[warp] = s0; redA1[warp] = s1; }
    __syncthreads();
    float tot0 = 0.f, tot1 = 0.f;
    #pragma unroll
    for (int i = 0; i < 8; i++) { tot0 += redA0[i]; tot1 += redA1[i]; }
    const float mu0 = tot0 * (1.0f / D_MODEL);
    const float mu1 = tot1 * (1.0f / D_MODEL);

    // pass 2: squared deviations (both experts, one barrier)
    float d0x = v0.x - mu0, d0y = v0.y - mu0, d0z = v0.z - mu0, d0w = v0.w - mu0;
    float d1x = v1.x - mu1, d1y = v1.y - mu1, d1z = v1.z - mu1, d1w = v1.w - mu1;
    float q0 = d0x * d0x + d0y * d0y + d0z * d0z + d0w * d0w;
    float q1 = d1x * d1x + d1y * d1y + d1z * d1z + d1w * d1w;
    #pragma unroll
    for (int o = 16; o; o >>= 1) {
        q0 += __shfl_xor_sync(0xffffffffu, q0, o);
        q1 += __shfl_xor_sync(0xffffffffu, q1, o);
    }
    if (lane == 0) { redB0[warp] = q0; redB1[warp] = q1; }
    __syncthreads();
    float tq0 = 0.f, tq1 = 0.f;
    #pragma unroll
    for (int i = 0; i < 8; i++) { tq0 += redB0[i]; tq1 += redB1[i]; }
    const float rstd0 = rsqrtf(tq0 * (1.0f / D_MODEL) + 1e-6f);
    const float rstd1 = rsqrtf(tq1 * (1.0f / D_MODEL) + 1e-6f);

    float4 g0  = ((const float4*)(gamma + (size_t)e0 * D_MODEL))[tid];
    float4 b0  = ((const float4*)(beta  + (size_t)e0 * D_MODEL))[tid];
    float4 g1  = ((const float4*)(gamma + (size_t)e1 * D_MODEL))[tid];
    float4 b1  = ((const float4*)(beta  + (size_t)e1 * D_MODEL))[tid];

    float4 o;
    o.x = w0 * (d0x * rstd0 * g0.x + b0.x) + w1 * (d1x * rstd1 * g1.x + b1.x);
    o.y = w0 * (d0y * rstd0 * g0.y + b0.y) + w1 * (d1y * rstd1 * g1.y + b1.y);
    o.z = w0 * (d0z * rstd0 * g0.z + b0.z) + w1 * (d1z * rstd1 * g1.z + b1.z);
    o.w = w0 * (d0w * rstd0 * g0.w + b0.w) + w1 * (d1w * rstd1 * g1.w + b1.w);
    ((float4*)(out + (size_t)tok * D_MODEL))[tid] = o;
}

// ---------------- launch ----------------
extern "C" void kernel_launch(void* const* d_in, const int* in_sizes, int n_in,
                              void* d_out, int out_size) {
    const float* x      = (const float*)d_in[0];
    const float* gate_w = (const float*)d_in[1];
    const float* w1     = (const float*)d_in[2];
    const float* b1     = (const float*)d_in[3];
    const float* w2     = (const float*)d_in[4];
    const float* b2     = (const float*)d_in[5];
    const float* gamma  = (const float*)d_in[6];
    const float* beta   = (const float*)d_in[7];

    __half *xh = nullptr, *w1h = nullptr, *w2h = nullptr, *hh = nullptr;
    cudaGetSymbolAddress((void**)&xh,  g_Xh);
    cudaGetSymbolAddress((void**)&w1h, g_W1h);
    cudaGetSymbolAddress((void**)&w2h, g_W2h);
    cudaGetSymbolAddress((void**)&hh,  g_Hh);

    cudaFuncSetAttribute(moe_gemm<D_MODEL, true>,
                         cudaFuncAttributeMaxDynamicSharedMemorySize, SMEM_DYN);
    cudaFuncSetAttribute(moe_gemm<D_FF, false>,
                         cudaFuncAttributeMaxDynamicSharedMemorySize, SMEM_DYN);

    init_counts_kernel<<<1, 32>>>();

    {
        int n4 = (N_TOKENS * D_MODEL) / 4;
        f2h_kernel<<<(n4 + 255) / 256, 256>>>((const float4*)x, (__half2*)xh, n4);
        n4 = (N_EXPERTS * D_FF * D_MODEL) / 4;
        f2h_kernel<<<(n4 + 255) / 256, 256>>>((const float4*)w1, (__half2*)w1h, n4);
        f2h_kernel<<<(n4 + 255) / 256, 256>>>((const float4*)w2, (__half2*)w2h, n4);
    }

    gate_kernel<<<N_TOKENS / 8, 256>>>(x, gate_w);

    dim3 g1(D_FF / BN, N_TOKENS / 128, N_EXPERTS);
    moe_gemm<D_MODEL, true><<<g1, 512, SMEM_DYN>>>(xh, w1h, b1, nullptr);

    dim3 g2(D_MODEL / BN, N_TOKENS / 128, N_EXPERTS);
    moe_gemm<D_FF, false><<<g2, 512, SMEM_DYN>>>(hh, w2h, b2, x);

    ln_kernel<<<N_TOKENS, 256>>>(gamma, beta, (float*)d_out);
}

// round 15
// speedup vs baseline: 1.6068x; 1.0089x over previous
#include <cuda_runtime.h>
#include <cuda_fp16.h>
#include <math.h>
#include <stdint.h>

#define N_TOKENS 16384
#define D_MODEL  1024
#define D_FF     2048
#define N_EXPERTS 4

// ---------------- scratch (device globals; no allocation allowed) ----------------
__device__ int    g_cnt[N_EXPERTS];
__device__ int    g_tok[N_EXPERTS * N_TOKENS];
__device__ int    g_eidx[2 * N_TOKENS];
__device__ int    g_slot[2 * N_TOKENS];
__device__ float  g_wsm [2 * N_TOKENS];
__device__ __half g_Xh [(size_t)N_TOKENS * D_MODEL];
__device__ __half g_W1h[(size_t)N_EXPERTS * D_FF * D_MODEL];
__device__ __half g_W2h[(size_t)N_EXPERTS * D_MODEL * D_FF];
__device__ __half g_Hh [(size_t)N_EXPERTS * N_TOKENS * D_FF];
__device__ __half g_Zh [(size_t)N_EXPERTS * N_TOKENS * D_MODEL];

__device__ __forceinline__ float gelu_exact(float v) {
    return 0.5f * v * (1.0f + erff(v * 0.70710678118654752440f));
}

__device__ __forceinline__ void mma_f16(float c[4], const uint32_t a[4], const uint32_t b[2]) {
    asm volatile(
        "mma.sync.aligned.m16n8k16.row.col.f32.f16.f16.f32 "
        "{%0,%1,%2,%3}, {%4,%5,%6,%7}, {%8,%9}, {%0,%1,%2,%3};"
        : "+f"(c[0]), "+f"(c[1]), "+f"(c[2]), "+f"(c[3])
        : "r"(a[0]), "r"(a[1]), "r"(a[2]), "r"(a[3]), "r"(b[0]), "r"(b[1]));
}

#define LDSM_X4(r0, r1, r2, r3, addr) \
    asm volatile("ldmatrix.sync.aligned.m8n8.x4.shared.b16 {%0,%1,%2,%3}, [%4];" \
                 : "=r"(r0), "=r"(r1), "=r"(r2), "=r"(r3) : "r"(addr))

__device__ __forceinline__ uint32_t smem_u32(const void* p) {
    uint32_t a;
    asm("{ .reg .u64 t; cvta.to.shared.u64 t, %1; cvt.u32.u64 %0, t; }" : "=r"(a) : "l"(p));
    return a;
}
__device__ __forceinline__ void cpasync16(uint32_t dst, const void* src) {
    asm volatile("cp.async.cg.shared.global [%0], [%1], 16;" :: "r"(dst), "l"(src));
}
__device__ __forceinline__ void cp_commit() {
    asm volatile("cp.async.commit_group;" ::: "memory");
}
__device__ __forceinline__ void cp_wait2() {
    asm volatile("cp.async.wait_group 2;" ::: "memory");
}
__device__ __forceinline__ void cp_wait0() {
    asm volatile("cp.async.wait_group 0;" ::: "memory");
}

// ---------------- init ----------------
__global__ void init_counts_kernel() {
    if (threadIdx.x < N_EXPERTS) g_cnt[threadIdx.x] = 0;
}

// ---------------- fused fp32 -> fp16 conversion for x, w1, w2 (one launch) ----------------
#define N4_X  ((N_TOKENS * D_MODEL) / 4)
#define N4_W  ((N_EXPERTS * D_FF * D_MODEL) / 4)
__global__ void __launch_bounds__(256) f2h_all_kernel(const float4* __restrict__ sx,
                                                      const float4* __restrict__ sw1,
                                                      const float4* __restrict__ sw2,
                                                      __half2* __restrict__ dx,
                                                      __half2* __restrict__ dw1,
                                                      __half2* __restrict__ dw2) {
    int i = blockIdx.x * 256 + threadIdx.x;
    const float4* src;
    __half2* dst;
    if (i < N4_X)              { src = sx;  dst = dx;  }
    else if (i < N4_X + N4_W)  { src = sw1; dst = dw1; i -= N4_X; }
    else                       { src = sw2; dst = dw2; i -= (N4_X + N4_W);
                                 if (i >= N4_W) return; }
    float4 v = src[i];
    dst[2 * i + 0] = __floats2half2_rn(v.x, v.y);
    dst[2 * i + 1] = __floats2half2_rn(v.z, v.w);
}

// ---------------- gating: scores, top-2, softmax, compaction ----------------
__global__ void __launch_bounds__(256) gate_kernel(const float* __restrict__ x,
                                                   const float* __restrict__ gate_w) {
    __shared__ float sgw[N_EXPERTS * D_MODEL];
    const int tid = threadIdx.x;
    for (int i = tid; i < N_EXPERTS * D_MODEL; i += 256) sgw[i] = gate_w[i];
    __syncthreads();

    const int warp = tid >> 5, lane = tid & 31;
    const int tok = blockIdx.x * 8 + warp;
    if (tok >= N_TOKENS) return;

    const float* xr = x + (size_t)tok * D_MODEL;
    float acc0 = 0.f, acc1 = 0.f, acc2 = 0.f, acc3 = 0.f;
    for (int k = lane; k < D_MODEL; k += 32) {
        float xv = xr[k];
        acc0 += xv * sgw[0 * D_MODEL + k];
        acc1 += xv * sgw[1 * D_MODEL + k];
        acc2 += xv * sgw[2 * D_MODEL + k];
        acc3 += xv * sgw[3 * D_MODEL + k];
    }
    #pragma unroll
    for (int o = 16; o; o >>= 1) {
        acc0 += __shfl_xor_sync(0xffffffffu, acc0, o);
        acc1 += __shfl_xor_sync(0xffffffffu, acc1, o);
        acc2 += __shfl_xor_sync(0xffffffffu, acc2, o);
        acc3 += __shfl_xor_sync(0xffffffffu, acc3, o);
    }
    if (lane == 0) {
        float s[4] = {acc0, acc1, acc2, acc3};
        int i0 = 0;
        #pragma unroll
        for (int e = 1; e < 4; e++) if (s[e] > s[i0]) i0 = e;
        int i1 = -1;
        #pragma unroll
        for (int e = 0; e < 4; e++) {
            if (e == i0) continue;
            if (i1 < 0 || s[e] > s[i1]) i1 = e;
        }
        float t  = expf(s[i1] - s[i0]);
        float p0 = 1.0f / (1.0f + t);
        float p1 = t / (1.0f + t);

        int sl0 = atomicAdd(&g_cnt[i0], 1);
        g_tok[i0 * N_TOKENS + sl0] = tok;
        int sl1 = atomicAdd(&g_cnt[i1], 1);
        g_tok[i1 * N_TOKENS + sl1] = tok;

        g_eidx[2 * tok + 0] = i0;  g_slot[2 * tok + 0] = sl0;  g_wsm[2 * tok + 0] = p0;
        g_eidx[2 * tok + 1] = i1;  g_slot[2 * tok + 1] = sl1;  g_wsm[2 * tok + 1] = p1;
    }
}

// ======================= FP16 tensor-core GEMMs (m16n8k16 + ldmatrix) =======================
// CTA 128(M) x 256(N), 512 threads = 16 warps (2 M x 8 N), warp tile 64x32.
// BK=32 halves, 4-stage cp.async pipeline (wait2), SROW=40 halves.
#define BK 32
#define SROW 40
#define STAGES 4
#define BN 256
#define A_STAGE_H (128 * SROW)                   // 5120 halves
#define A_STAGE_B (A_STAGE_H * 2)                // 10240 bytes
#define B_STAGE_H (BN * SROW)                    // 10240 halves
#define STAGE_H   (A_STAGE_H + B_STAGE_H)        // 15360 halves
#define STAGE_B   (STAGE_H * 2)                  // 30720 bytes
#define SMEM_DYN  (STAGES * STAGE_B)             // 122880 bytes

template<int KDIM, bool G1>
__global__ void __launch_bounds__(512, 1) moe_gemm(
    const __half* __restrict__ Asrc, const __half* __restrict__ Wh,
    const float* __restrict__ bias, const float* __restrict__ resid)
{
    const int e   = blockIdx.z;
    const int cnt = g_cnt[e];
    const int m0  = blockIdx.y * 128;
    if (m0 >= cnt) return;
    const int n0  = blockIdx.x * BN;

    extern __shared__ __half smem[];
    __shared__ int stok[128];

    const int tid = threadIdx.x;
    if (tid < 128) {
        int m = m0 + tid;
        stok[tid] = g_tok[e * N_TOKENS + (m < cnt ? m : cnt - 1)];
    }
    __syncthreads();

    // ---- loader mapping: thread t -> A row t>>2 quad t&3; B rows t>>2 and 128+(t>>2) ----
    const int lrow = tid >> 2;       // 0..127
    const int quad = tid & 3;        // 16B chunk within 32-half row

    const __half* aptr;
    if (G1) {
        aptr = Asrc + (size_t)stok[lrow] * KDIM + quad * 8;
    } else {
        int mr = m0 + lrow; if (mr >= cnt) mr = cnt - 1;
        aptr = Asrc + ((size_t)e * N_TOKENS + mr) * KDIM + quad * 8;
    }
    const __half* wbase = Wh + (size_t)e * ((size_t)D_FF * D_MODEL);
    const __half* bptr0 = wbase + (size_t)(n0 + lrow)       * KDIM + quad * 8;
    const __half* bptr1 = wbase + (size_t)(n0 + 128 + lrow) * KDIM + quad * 8;

    const uint32_t sbase = smem_u32(smem);
    const uint32_t aoff  = (uint32_t)(lrow * SROW + quad * 8) * 2u;
    const uint32_t boff0 = (uint32_t)A_STAGE_B + aoff;
    const uint32_t boff1 = boff0 + (uint32_t)(128 * SROW * 2);

    auto issue = [&](int t, int s) {
        const int kt = t * BK;
        const uint32_t sa = sbase + (uint32_t)s * STAGE_B;
        cpasync16(sa + aoff,  aptr  + kt);
        cpasync16(sa + boff0, bptr0 + kt);
        cpasync16(sa + boff1, bptr1 + kt);
    };

    // ---- compute mapping: 16 warps = 2 (M) x 8 (N), warp tile 64x32 ----
    const int warp = tid >> 5, lane = tid & 31;
    const int wm = (warp & 1) * 64;
    const int wn = (warp >> 1) * 32;
    const int gid = lane >> 2, tig = lane & 3;

    uint32_t a_lm[4];
    #pragma unroll
    for (int mt = 0; mt < 4; mt++)
        a_lm[mt] = (uint32_t)((wm + mt * 16 + (lane & 15)) * SROW + ((lane >> 4) * 8)) * 2u;
    const uint32_t b_lm = (uint32_t)((wn + lane) * SROW) * 2u + (uint32_t)A_STAGE_B;

    float acc[4][4][4];
    #pragma unroll
    for (int mt = 0; mt < 4; mt++)
        #pragma unroll
        for (int nt = 0; nt < 4; nt++)
            #pragma unroll
            for (int r = 0; r < 4; r++) acc[mt][nt][r] = 0.f;

    constexpr int T = KDIM / BK;

    issue(0, 0); cp_commit();
    issue(1, 1); cp_commit();
    issue(2, 2); cp_commit();

    for (int t = 0; t < T; t++) {
        const int s = t % STAGES;
        if (t + 3 < T) cp_wait2(); else cp_wait0();
        __syncthreads();
        if (t + 3 < T) { issue(t + 3, (t + 3) % STAGES); cp_commit(); }

        const uint32_t sa = sbase + (uint32_t)s * STAGE_B;

        #pragma unroll
        for (int ks = 0; ks < 2; ks++) {
            const uint32_t kb = (uint32_t)(ks * 16 * 2);   // byte offset of 16-col block
            uint32_t af[4][4], bf[4][2];
            #pragma unroll
            for (int mt = 0; mt < 4; mt++)
                LDSM_X4(af[mt][0], af[mt][1], af[mt][2], af[mt][3], sa + a_lm[mt] + kb);
            {
                uint32_t r0, r1, r2, r3;
                LDSM_X4(r0, r1, r2, r3, sa + b_lm + kb);
                bf[0][0] = r0; bf[1][0] = r1; bf[2][0] = r2; bf[3][0] = r3;
                LDSM_X4(r0, r1, r2, r3, sa + b_lm + kb + 16u);
                bf[0][1] = r0; bf[1][1] = r1; bf[2][1] = r2; bf[3][1] = r3;
            }
            #pragma unroll
            for (int mt = 0; mt < 4; mt++)
                #pragma unroll
                for (int nt = 0; nt < 4; nt++)
                    mma_f16(acc[mt][nt], af[mt], bf[nt]);
        }
    }

    // ---- epilogue ----
    #pragma unroll
    for (int nt = 0; nt < 4; nt++) {
        const int nl = wn + nt * 8 + tig * 2;
        if (G1) {
            float2 bb = *(const float2*)(bias + (size_t)e * D_FF + n0 + nl);
            #pragma unroll
            for (int mt = 0; mt < 4; mt++) {
                int mA = m0 + wm + mt * 16 + gid;
                if (mA < cnt) {
                    float vx = gelu_exact(acc[mt][nt][0] + bb.x);
                    float vy = gelu_exact(acc[mt][nt][1] + bb.y);
                    *(__half2*)(g_Hh + ((size_t)e * N_TOKENS + mA) * D_FF + n0 + nl)
                        = __floats2half2_rn(vx, vy);
                }
                int mB = mA + 8;
                if (mB < cnt) {
                    float vx = gelu_exact(acc[mt][nt][2] + bb.x);
                    float vy = gelu_exact(acc[mt][nt][3] + bb.y);
                    *(__half2*)(g_Hh + ((size_t)e * N_TOKENS + mB) * D_FF + n0 + nl)
                        = __floats2half2_rn(vx, vy);
                }
            }
        } else {
            float2 bb = *(const float2*)(bias + (size_t)e * D_MODEL + n0 + nl);
            #pragma unroll
            for (int mt = 0; mt < 4; mt++) {
                int mA = m0 + wm + mt * 16 + gid;
                if (mA < cnt) {
                    int tok = stok[wm + mt * 16 + gid];
                    float2 xv = *(const float2*)(resid + (size_t)tok * D_MODEL + n0 + nl);
                    *(__half2*)(g_Zh + ((size_t)e * N_TOKENS + mA) * D_MODEL + n0 + nl)
                        = __floats2half2_rn(acc[mt][nt][0] + bb.x + xv.x,
                                            acc[mt][nt][1] + bb.y + xv.y);
                }
                int mB = mA + 8;
                if (mB < cnt) {
                    int tok = stok[wm + mt * 16 + gid + 8];
                    float2 xv = *(const float2*)(resid + (size_t)tok * D_MODEL + n0 + nl);
                    *(__half2*)(g_Zh + ((size_t)e * N_TOKENS + mB) * D_MODEL + n0 + nl)
                        = __floats2half2_rn(acc[mt][nt][2] + bb.x + xv.x,
                                            acc[mt][nt][3] + bb.y + xv.y);
                }
            }
        }
    }
}

// -------- LayerNorm: one block per token, BOTH experts in one pass, fp16 Z in --------
__global__ void __launch_bounds__(256) ln_kernel(const float* __restrict__ gamma,
                                                 const float* __restrict__ beta,
                                                 float* __restrict__ out) {
    const int tok = blockIdx.x;
    const int tid  = threadIdx.x;
    const int lane = tid & 31, warp = tid >> 5;

    __shared__ float redA0[8];
    __shared__ float redA1[8];
    __shared__ float redB0[8];
    __shared__ float redB1[8];

    const int   e0 = g_eidx[2 * tok + 0], e1 = g_eidx[2 * tok + 1];
    const int   sl0 = g_slot[2 * tok + 0], sl1 = g_slot[2 * tok + 1];
    const float w0 = g_wsm[2 * tok + 0], w1 = g_wsm[2 * tok + 1];

    // load 4 halves per expert per thread (uint2 = 2x half2)
    uint2 h0 = ((const uint2*)(g_Zh + ((size_t)e0 * N_TOKENS + sl0) * D_MODEL))[tid];
    uint2 h1 = ((const uint2*)(g_Zh + ((size_t)e1 * N_TOKENS + sl1) * D_MODEL))[tid];
    float2 p0a = __half22float2(*(__half2*)&h0.x), p0b = __half22float2(*(__half2*)&h0.y);
    float2 p1a = __half22float2(*(__half2*)&h1.x), p1b = __half22float2(*(__half2*)&h1.y);
    float4 v0 = make_float4(p0a.x, p0a.y, p0b.x, p0b.y);
    float4 v1 = make_float4(p1a.x, p1a.y, p1b.x, p1b.y);

    // pass 1: sums (both experts, one barrier)
    float s0 = v0.x + v0.y + v0.z + v0.w;
    float s1 = v1.x + v1.y + v1.z + v1.w;
    #pragma unroll
    for (int o = 16; o; o >>= 1) {
        s0 += __shfl_xor_sync(0xffffffffu, s0, o);
        s1 += __shfl_xor_sync(0xffffffffu, s1, o);
    }
    if (lane == 0) { redA0[warp] = s0; redA1[warp] = s1; }
    __syncthreads();
    float tot0 = 0.f, tot1 = 0.f;
    #pragma unroll
    for (int i = 0; i < 8; i++) { tot0 += redA0[i]; tot1 += redA1[i]; }
    const float mu0 = tot0 * (1.0f / D_MODEL);
    const float mu1 = tot1 * (1.0f / D_MODEL);

    // pass 2: squared deviations (both experts, one barrier)
    float d0x = v0.x - mu0, d0y = v0.y - mu0, d0z = v0.z - mu0, d0w = v0.w - mu0;
    float d1x = v1.x - mu1, d1y = v1.y - mu1, d1z = v1.z - mu1, d1w = v1.w - mu1;
    float q0 = d0x * d0x + d0y * d0y + d0z * d0z + d0w * d0w;
    float q1 = d1x * d1x + d1y * d1y + d1z * d1z + d1w * d1w;
    #pragma unroll
    for (int o = 16; o; o >>= 1) {
        q0 += __shfl_xor_sync(0xffffffffu, q0, o);
        q1 += __shfl_xor_sync(0xffffffffu, q1, o);
    }
    if (lane == 0) { redB0[warp] = q0; redB1[warp] = q1; }
    __syncthreads();
    float tq0 = 0.f, tq1 = 0.f;
    #pragma unroll
    for (int i = 0; i < 8; i++) { tq0 += redB0[i]; tq1 += redB1[i]; }
    const float rstd0 = rsqrtf(tq0 * (1.0f / D_MODEL) + 1e-6f);
    const float rstd1 = rsqrtf(tq1 * (1.0f / D_MODEL) + 1e-6f);

    float4 g0  = ((const float4*)(gamma + (size_t)e0 * D_MODEL))[tid];
    float4 b0  = ((const float4*)(beta  + (size_t)e0 * D_MODEL))[tid];
    float4 g1  = ((const float4*)(gamma + (size_t)e1 * D_MODEL))[tid];
    float4 b1  = ((const float4*)(beta  + (size_t)e1 * D_MODEL))[tid];

    float4 o;
    o.x = w0 * (d0x * rstd0 * g0.x + b0.x) + w1 * (d1x * rstd1 * g1.x + b1.x);
    o.y = w0 * (d0y * rstd0 * g0.y + b0.y) + w1 * (d1y * rstd1 * g1.y + b1.y);
    o.z = w0 * (d0z * rstd0 * g0.z + b0.z) + w1 * (d1z * rstd1 * g1.z + b1.z);
    o.w = w0 * (d0w * rstd0 * g0.w + b0.w) + w1 * (d1w * rstd1 * g1.w + b1.w);
    ((float4*)(out + (size_t)tok * D_MODEL))[tid] = o;
}

// ---------------- launch ----------------
extern "C" void kernel_launch(void* const* d_in, const int* in_sizes, int n_in,
                              void* d_out, int out_size) {
    const float* x      = (const float*)d_in[0];
    const float* gate_w = (const float*)d_in[1];
    const float* w1     = (const float*)d_in[2];
    const float* b1     = (const float*)d_in[3];
    const float* w2     = (const float*)d_in[4];
    const float* b2     = (const float*)d_in[5];
    const float* gamma  = (const float*)d_in[6];
    const float* beta   = (const float*)d_in[7];

    __half *xh = nullptr, *w1h = nullptr, *w2h = nullptr, *hh = nullptr;
    cudaGetSymbolAddress((void**)&xh,  g_Xh);
    cudaGetSymbolAddress((void**)&w1h, g_W1h);
    cudaGetSymbolAddress((void**)&w2h, g_W2h);
    cudaGetSymbolAddress((void**)&hh,  g_Hh);

    cudaFuncSetAttribute(moe_gemm<D_MODEL, true>,
                         cudaFuncAttributeMaxDynamicSharedMemorySize, SMEM_DYN);
    cudaFuncSetAttribute(moe_gemm<D_FF, false>,
                         cudaFuncAttributeMaxDynamicSharedMemorySize, SMEM_DYN);

    init_counts_kernel<<<1, 32>>>();

    {
        int n4_total = N4_X + 2 * N4_W;
        f2h_all_kernel<<<(n4_total + 255) / 256, 256>>>(
            (const float4*)x, (const float4*)w1, (const float4*)w2,
            (__half2*)xh, (__half2*)w1h, (__half2*)w2h);
    }

    gate_kernel<<<N_TOKENS / 8, 256>>>(x, gate_w);

    dim3 g1(D_FF / BN, N_TOKENS / 128, N_EXPERTS);
    moe_gemm<D_MODEL, true><<<g1, 512, SMEM_DYN>>>(xh, w1h, b1, nullptr);

    dim3 g2(D_MODEL / BN, N_TOKENS / 128, N_EXPERTS);
    moe_gemm<D_FF, false><<<g2, 512, SMEM_DYN>>>(hh, w2h, b2, x);

    ln_kernel<<<N_TOKENS, 256>>>(gamma, beta, (float*)d_out);
}

// round 17
// speedup vs baseline: 1.6624x; 1.0346x over previous
#include <cuda_runtime.h>
#include <cuda_fp16.h>
#include <math.h>
#include <stdint.h>

#define N_TOKENS 16384
#define D_MODEL  1024
#define D_FF     2048
#define N_EXPERTS 4

// ---------------- scratch (device globals; no allocation allowed) ----------------
__device__ int    g_cnt[N_EXPERTS];
__device__ int    g_tok[N_EXPERTS * N_TOKENS];
__device__ int    g_eidx[2 * N_TOKENS];
__device__ int    g_slot[2 * N_TOKENS];
__device__ float  g_wsm [2 * N_TOKENS];
__device__ __half g_Xh [(size_t)N_TOKENS * D_MODEL];
__device__ __half g_W1h[(size_t)N_EXPERTS * D_FF * D_MODEL];
__device__ __half g_W2h[(size_t)N_EXPERTS * D_MODEL * D_FF];
__device__ __half g_Hh [(size_t)N_EXPERTS * N_TOKENS * D_FF];
__device__ __half g_Zh [(size_t)N_EXPERTS * N_TOKENS * D_MODEL];

// Fast exact-erf GELU: A&S 7.1.26 polynomial, |erf err| <= 1.5e-7 (well under
// the 5e-4 fp16 storage rounding). MUFU rcp/ex2 paths.
__device__ __forceinline__ float gelu_exact(float v) {
    float x  = v * 0.70710678118654752440f;
    float ax = fabsf(x);
    float t  = __fdividef(1.0f, fmaf(0.3275911f, ax, 1.0f));
    float p  = fmaf(t, 1.061405429f, -1.453152027f);
    p = fmaf(t, p, 1.421413741f);
    p = fmaf(t, p, -0.284496736f);
    p = fmaf(t, p, 0.254829592f);
    p = p * t;
    float e  = __expf(-ax * ax);
    float er = fmaf(-p, e, 1.0f);
    er = copysignf(er, x);
    return 0.5f * v * (1.0f + er);
}

__device__ __forceinline__ void mma_f16(float c[4], const uint32_t a[4], const uint32_t b[2]) {
    asm volatile(
        "mma.sync.aligned.m16n8k16.row.col.f32.f16.f16.f32 "
        "{%0,%1,%2,%3}, {%4,%5,%6,%7}, {%8,%9}, {%0,%1,%2,%3};"
        : "+f"(c[0]), "+f"(c[1]), "+f"(c[2]), "+f"(c[3])
        : "r"(a[0]), "r"(a[1]), "r"(a[2]), "r"(a[3]), "r"(b[0]), "r"(b[1]));
}

#define LDSM_X4(r0, r1, r2, r3, addr) \
    asm volatile("ldmatrix.sync.aligned.m8n8.x4.shared.b16 {%0,%1,%2,%3}, [%4];" \
                 : "=r"(r0), "=r"(r1), "=r"(r2), "=r"(r3) : "r"(addr))

__device__ __forceinline__ uint32_t smem_u32(const void* p) {
    uint32_t a;
    asm("{ .reg .u64 t; cvta.to.shared.u64 t, %1; cvt.u32.u64 %0, t; }" : "=r"(a) : "l"(p));
    return a;
}
__device__ __forceinline__ void cpasync16(uint32_t dst, const void* src) {
    asm volatile("cp.async.cg.shared.global [%0], [%1], 16;" :: "r"(dst), "l"(src));
}
__device__ __forceinline__ void cp_commit() {
    asm volatile("cp.async.commit_group;" ::: "memory");
}
__device__ __forceinline__ void cp_wait2() {
    asm volatile("cp.async.wait_group 2;" ::: "memory");
}
__device__ __forceinline__ void cp_wait0() {
    asm volatile("cp.async.wait_group 0;" ::: "memory");
}

// ---------------- init ----------------
__global__ void init_counts_kernel() {
    if (threadIdx.x < N_EXPERTS) g_cnt[threadIdx.x] = 0;
}

// ---------------- fused prep: gate (blocks 0..GATE_BLOCKS-1) + f2h (rest) ----------------
#define GATE_BLOCKS (N_TOKENS / 8)
#define N4_X  ((N_TOKENS * D_MODEL) / 4)
#define N4_W  ((N_EXPERTS * D_FF * D_MODEL) / 4)
#define F2H_BLOCKS ((N4_X + 2 * N4_W + 255) / 256)

__global__ void __launch_bounds__(256) prep_kernel(const float* __restrict__ x,
                                                   const float* __restrict__ gate_w,
                                                   const float* __restrict__ w1,
                                                   const float* __restrict__ w2) {
    __shared__ float sgw[N_EXPERTS * D_MODEL];
    const int tid = threadIdx.x;

    if (blockIdx.x >= GATE_BLOCKS) {
        // ---------- f2h part: convert x, w1, w2 ----------
        int i = (blockIdx.x - GATE_BLOCKS) * 256 + tid;
        const float4* src;
        __half2* dst;
        if (i < N4_X) {
            src = (const float4*)x;
            dst = (__half2*)g_Xh;
        } else if (i < N4_X + N4_W) {
            src = (const float4*)w1;
            dst = (__half2*)g_W1h;
            i -= N4_X;
        } else {
            i -= (N4_X + N4_W);
            if (i >= N4_W) return;
            src = (const float4*)w2;
            dst = (__half2*)g_W2h;
        }
        float4 v = src[i];
        dst[2 * i + 0] = __floats2half2_rn(v.x, v.y);
        dst[2 * i + 1] = __floats2half2_rn(v.z, v.w);
        return;
    }

    // ---------- gate part ----------
    for (int i = tid; i < N_EXPERTS * D_MODEL; i += 256) sgw[i] = gate_w[i];
    __syncthreads();

    const int warp = tid >> 5, lane = tid & 31;
    const int tok = blockIdx.x * 8 + warp;
    if (tok >= N_TOKENS) return;

    const float* xr = x + (size_t)tok * D_MODEL;
    float acc0 = 0.f, acc1 = 0.f, acc2 = 0.f, acc3 = 0.f;
    for (int k = lane; k < D_MODEL; k += 32) {
        float xv = xr[k];
        acc0 += xv * sgw[0 * D_MODEL + k];
        acc1 += xv * sgw[1 * D_MODEL + k];
        acc2 += xv * sgw[2 * D_MODEL + k];
        acc3 += xv * sgw[3 * D_MODEL + k];
    }
    #pragma unroll
    for (int o = 16; o; o >>= 1) {
        acc0 += __shfl_xor_sync(0xffffffffu, acc0, o);
        acc1 += __shfl_xor_sync(0xffffffffu, acc1, o);
        acc2 += __shfl_xor_sync(0xffffffffu, acc2, o);
        acc3 += __shfl_xor_sync(0xffffffffu, acc3, o);
    }
    if (lane == 0) {
        float s[4] = {acc0, acc1, acc2, acc3};
        int i0 = 0;
        #pragma unroll
        for (int e = 1; e < 4; e++) if (s[e] > s[i0]) i0 = e;
        int i1 = -1;
        #pragma unroll
        for (int e = 0; e < 4; e++) {
            if (e == i0) continue;
            if (i1 < 0 || s[e] > s[i1]) i1 = e;
        }
        float t  = expf(s[i1] - s[i0]);
        float p0 = 1.0f / (1.0f + t);
        float p1 = t / (1.0f + t);

        int sl0 = atomicAdd(&g_cnt[i0], 1);
        g_tok[i0 * N_TOKENS + sl0] = tok;
        int sl1 = atomicAdd(&g_cnt[i1], 1);
        g_tok[i1 * N_TOKENS + sl1] = tok;

        g_eidx[2 * tok + 0] = i0;  g_slot[2 * tok + 0] = sl0;  g_wsm[2 * tok + 0] = p0;
        g_eidx[2 * tok + 1] = i1;  g_slot[2 * tok + 1] = sl1;  g_wsm[2 * tok + 1] = p1;
    }
}

// ======================= FP16 tensor-core GEMMs (m16n8k16 + ldmatrix) =======================
// CTA 128(M) x 256(N), 512 threads = 16 warps (2 M x 8 N), warp tile 64x32.
// BK=32 halves, 4-stage cp.async pipeline (wait2), SROW=40 halves.
#define BK 32
#define SROW 40
#define STAGES 4
#define BN 256
#define A_STAGE_H (128 * SROW)                   // 5120 halves
#define A_STAGE_B (A_STAGE_H * 2)                // 10240 bytes
#define B_STAGE_H (BN * SROW)                    // 10240 halves
#define STAGE_H   (A_STAGE_H + B_STAGE_H)        // 15360 halves
#define STAGE_B   (STAGE_H * 2)                  // 30720 bytes
#define SMEM_DYN  (STAGES * STAGE_B)             // 122880 bytes

template<int KDIM, bool G1>
__global__ void __launch_bounds__(512, 1) moe_gemm(
    const __half* __restrict__ Asrc, const __half* __restrict__ Wh,
    const float* __restrict__ bias, const float* __restrict__ resid)
{
    const int e   = blockIdx.z;
    const int cnt = g_cnt[e];
    const int m0  = blockIdx.y * 128;
    if (m0 >= cnt) return;
    const int n0  = blockIdx.x * BN;

    extern __shared__ __half smem[];
    __shared__ int stok[128];

    const int tid = threadIdx.x;
    if (tid < 128) {
        int m = m0 + tid;
        stok[tid] = g_tok[e * N_TOKENS + (m < cnt ? m : cnt - 1)];
    }
    __syncthreads();

    // ---- loader mapping: thread t -> A row t>>2 quad t&3; B rows t>>2 and 128+(t>>2) ----
    const int lrow = tid >> 2;       // 0..127
    const int quad = tid & 3;        // 16B chunk within 32-half row

    const __half* aptr;
    if (G1) {
        aptr = Asrc + (size_t)stok[lrow] * KDIM + quad * 8;
    } else {
        int mr = m0 + lrow; if (mr >= cnt) mr = cnt - 1;
        aptr = Asrc + ((size_t)e * N_TOKENS + mr) * KDIM + quad * 8;
    }
    const __half* wbase = Wh + (size_t)e * ((size_t)D_FF * D_MODEL);
    const __half* bptr0 = wbase + (size_t)(n0 + lrow)       * KDIM + quad * 8;
    const __half* bptr1 = wbase + (size_t)(n0 + 128 + lrow) * KDIM + quad * 8;

    const uint32_t sbase = smem_u32(smem);
    const uint32_t aoff  = (uint32_t)(lrow * SROW + quad * 8) * 2u;
    const uint32_t boff0 = (uint32_t)A_STAGE_B + aoff;
    const uint32_t boff1 = boff0 + (uint32_t)(128 * SROW * 2);

    auto issue = [&](int t, int s) {
        const int kt = t * BK;
        const uint32_t sa = sbase + (uint32_t)s * STAGE_B;
        cpasync16(sa + aoff,  aptr  + kt);
        cpasync16(sa + boff0, bptr0 + kt);
        cpasync16(sa + boff1, bptr1 + kt);
    };

    // ---- compute mapping: 16 warps = 2 (M) x 8 (N), warp tile 64x32 ----
    const int warp = tid >> 5, lane = tid & 31;
    const int wm = (warp & 1) * 64;
    const int wn = (warp >> 1) * 32;
    const int gid = lane >> 2, tig = lane & 3;

    uint32_t a_lm[4];
    #pragma unroll
    for (int mt = 0; mt < 4; mt++)
        a_lm[mt] = (uint32_t)((wm + mt * 16 + (lane & 15)) * SROW + ((lane >> 4) * 8)) * 2u;
    const uint32_t b_lm = (uint32_t)((wn + lane) * SROW) * 2u + (uint32_t)A_STAGE_B;

    float acc[4][4][4];
    #pragma unroll
    for (int mt = 0; mt < 4; mt++)
        #pragma unroll
        for (int nt = 0; nt < 4; nt++)
            #pragma unroll
            for (int r = 0; r < 4; r++) acc[mt][nt][r] = 0.f;

    constexpr int T = KDIM / BK;

    issue(0, 0); cp_commit();
    issue(1, 1); cp_commit();
    issue(2, 2); cp_commit();

    for (int t = 0; t < T; t++) {
        const int s = t % STAGES;
        if (t + 3 < T) cp_wait2(); else cp_wait0();
        __syncthreads();
        if (t + 3 < T) { issue(t + 3, (t + 3) % STAGES); cp_commit(); }

        const uint32_t sa = sbase + (uint32_t)s * STAGE_B;

        #pragma unroll
        for (int ks = 0; ks < 2; ks++) {
            const uint32_t kb = (uint32_t)(ks * 16 * 2);   // byte offset of 16-col block
            uint32_t af[4][4], bf[4][2];
            #pragma unroll
            for (int mt = 0; mt < 4; mt++)
                LDSM_X4(af[mt][0], af[mt][1], af[mt][2], af[mt][3], sa + a_lm[mt] + kb);
            {
                uint32_t r0, r1, r2, r3;
                LDSM_X4(r0, r1, r2, r3, sa + b_lm + kb);
                bf[0][0] = r0; bf[1][0] = r1; bf[2][0] = r2; bf[3][0] = r3;
                LDSM_X4(r0, r1, r2, r3, sa + b_lm + kb + 16u);
                bf[0][1] = r0; bf[1][1] = r1; bf[2][1] = r2; bf[3][1] = r3;
            }
            #pragma unroll
            for (int mt = 0; mt < 4; mt++)
                #pragma unroll
                for (int nt = 0; nt < 4; nt++)
                    mma_f16(acc[mt][nt], af[mt], bf[nt]);
        }
    }

    // ---- epilogue ----
    #pragma unroll
    for (int nt = 0; nt < 4; nt++) {
        const int nl = wn + nt * 8 + tig * 2;
        if (G1) {
            float2 bb = *(const float2*)(bias + (size_t)e * D_FF + n0 + nl);
            #pragma unroll
            for (int mt = 0; mt < 4; mt++) {
                int mA = m0 + wm + mt * 16 + gid;
                if (mA < cnt) {
                    float vx = gelu_exact(acc[mt][nt][0] + bb.x);
                    float vy = gelu_exact(acc[mt][nt][1] + bb.y);
                    *(__half2*)(g_Hh + ((size_t)e * N_TOKENS + mA) * D_FF + n0 + nl)
                        = __floats2half2_rn(vx, vy);
                }
                int mB = mA + 8;
                if (mB < cnt) {
                    float vx = gelu_exact(acc[mt][nt][2] + bb.x);
                    float vy = gelu_exact(acc[mt][nt][3] + bb.y);
                    *(__half2*)(g_Hh + ((size_t)e * N_TOKENS + mB) * D_FF + n0 + nl)
                        = __floats2half2_rn(vx, vy);
                }
            }
        } else {
            float2 bb = *(const float2*)(bias + (size_t)e * D_MODEL + n0 + nl);
            #pragma unroll
            for (int mt = 0; mt < 4; mt++) {
                int mA = m0 + wm + mt * 16 + gid;
                if (mA < cnt) {
                    int tok = stok[wm + mt * 16 + gid];
                    float2 xv = *(const float2*)(resid + (size_t)tok * D_MODEL + n0 + nl);
                    *(__half2*)(g_Zh + ((size_t)e * N_TOKENS + mA) * D_MODEL + n0 + nl)
                        = __floats2half2_rn(acc[mt][nt][0] + bb.x + xv.x,
                                            acc[mt][nt][1] + bb.y + xv.y);
                }
                int mB = mA + 8;
                if (mB < cnt) {
                    int tok = stok[wm + mt * 16 + gid + 8];
                    float2 xv = *(const float2*)(resid + (size_t)tok * D_MODEL + n0 + nl);
                    *(__half2*)(g_Zh + ((size_t)e * N_TOKENS + mB) * D_MODEL + n0 + nl)
                        = __floats2half2_rn(acc[mt][nt][2] + bb.x + xv.x,
                                            acc[mt][nt][3] + bb.y + xv.y);
                }
            }
        }
    }
}

// -------- LayerNorm: one block per token, BOTH experts in one pass, fp16 Z in --------
__global__ void __launch_bounds__(256) ln_kernel(const float* __restrict__ gamma,
                                                 const float* __restrict__ beta,
                                                 float* __restrict__ out) {
    const int tok = blockIdx.x;
    const int tid  = threadIdx.x;
    const int lane = tid & 31, warp = tid >> 5;

    __shared__ float redA0[8];
    __shared__ float redA1[8];
    __shared__ float redB0[8];
    __shared__ float redB1[8];

    const int   e0 = g_eidx[2 * tok + 0], e1 = g_eidx[2 * tok + 1];
    const int   sl0 = g_slot[2 * tok + 0], sl1 = g_slot[2 * tok + 1];
    const float w0 = g_wsm[2 * tok + 0], w1 = g_wsm[2 * tok + 1];

    uint2 h0 = ((const uint2*)(g_Zh + ((size_t)e0 * N_TOKENS + sl0) * D_MODEL))[tid];
    uint2 h1 = ((const uint2*)(g_Zh + ((size_t)e1 * N_TOKENS + sl1) * D_MODEL))[tid];
    float2 p0a = __half22float2(*(__half2*)&h0.x), p0b = __half22float2(*(__half2*)&h0.y);
    float2 p1a = __half22float2(*(__half2*)&h1.x), p1b = __half22float2(*(__half2*)&h1.y);
    float4 v0 = make_float4(p0a.x, p0a.y, p0b.x, p0b.y);
    float4 v1 = make_float4(p1a.x, p1a.y, p1b.x, p1b.y);

    float s0 = v0.x + v0.y + v0.z + v0.w;
    float s1 = v1.x + v1.y + v1.z + v1.w;
    #pragma unroll
    for (int o = 16; o; o >>= 1) {
        s0 += __shfl_xor_sync(0xffffffffu, s0, o);
        s1 += __shfl_xor_sync(0xffffffffu, s1, o);
    }
    if (lane == 0) { redA0[warp] = s0; redA1[warp] = s1; }
    __syncthreads();
    float tot0 = 0.f, tot1 = 0.f;
    #pragma unroll
    for (int i = 0; i < 8; i++) { tot0 += redA0[i]; tot1 += redA1[i]; }
    const float mu0 = tot0 * (1.0f / D_MODEL);
    const float mu1 = tot1 * (1.0f / D_MODEL);

    float d0x = v0.x - mu0, d0y = v0.y - mu0, d0z = v0.z - mu0, d0w = v0.w - mu0;
    float d1x = v1.x - mu1, d1y = v1.y - mu1, d1z = v1.z - mu1, d1w = v1.w - mu1;
    float q0 = d0x * d0x + d0y * d0y + d0z * d0z + d0w * d0w;
    float q1 = d1x * d1x + d1y * d1y + d1z * d1z + d1w * d1w;
    #pragma unroll
    for (int o = 16; o; o >>= 1) {
        q0 += __shfl_xor_sync(0xffffffffu, q0, o);
        q1 += __shfl_xor_sync(0xffffffffu, q1, o);
    }
    if (lane == 0) { redB0[warp] = q0; redB1[warp] = q1; }
    __syncthreads();
    float tq0 = 0.f, tq1 = 0.f;
    #pragma unroll
    for (int i = 0; i < 8; i++) { tq0 += redB0[i]; tq1 += redB1[i]; }
    const float rstd0 = rsqrtf(tq0 * (1.0f / D_MODEL) + 1e-6f);
    const float rstd1 = rsqrtf(tq1 * (1.0f / D_MODEL) + 1e-6f);

    float4 g0  = ((const float4*)(gamma + (size_t)e0 * D_MODEL))[tid];
    float4 b0  = ((const float4*)(beta  + (size_t)e0 * D_MODEL))[tid];
    float4 g1  = ((const float4*)(gamma + (size_t)e1 * D_MODEL))[tid];
    float4 b1  = ((const float4*)(beta  + (size_t)e1 * D_MODEL))[tid];

    float4 o;
    o.x = w0 * (d0x * rstd0 * g0.x + b0.x) + w1 * (d1x * rstd1 * g1.x + b1.x);
    o.y = w0 * (d0y * rstd0 * g0.y + b0.y) + w1 * (d1y * rstd1 * g1.y + b1.y);
    o.z = w0 * (d0z * rstd0 * g0.z + b0.z) + w1 * (d1z * rstd1 * g1.z + b1.z);
    o.w = w0 * (d0w * rstd0 * g0.w + b0.w) + w1 * (d1w * rstd1 * g1.w + b1.w);
    ((float4*)(out + (size_t)tok * D_MODEL))[tid] = o;
}

// ---------------- launch ----------------
extern "C" void kernel_launch(void* const* d_in, const int* in_sizes, int n_in,
                              void* d_out, int out_size) {
    const float* x      = (const float*)d_in[0];
    const float* gate_w = (const float*)d_in[1];
    const float* w1     = (const float*)d_in[2];
    const float* b1     = (const float*)d_in[3];
    const float* w2     = (const float*)d_in[4];
    const float* b2     = (const float*)d_in[5];
    const float* gamma  = (const float*)d_in[6];
    const float* beta   = (const float*)d_in[7];

    __half *xh = nullptr, *w1h = nullptr, *w2h = nullptr, *hh = nullptr;
    cudaGetSymbolAddress((void**)&xh,  g_Xh);
    cudaGetSymbolAddress((void**)&w1h, g_W1h);
    cudaGetSymbolAddress((void**)&w2h, g_W2h);
    cudaGetSymbolAddress((void**)&hh,  g_Hh);

    cudaFuncSetAttribute(moe_gemm<D_MODEL, true>,
                         cudaFuncAttributeMaxDynamicSharedMemorySize, SMEM_DYN);
    cudaFuncSetAttribute(moe_gemm<D_FF, false>,
                         cudaFuncAttributeMaxDynamicSharedMemorySize, SMEM_DYN);

    init_counts_kernel<<<1, 32>>>();

    prep_kernel<<<GATE_BLOCKS + F2H_BLOCKS, 256>>>(x, gate_w, w1, w2);

    dim3 g1(D_FF / BN, N_TOKENS / 128, N_EXPERTS);
    moe_gemm<D_MODEL, true><<<g1, 512, SMEM_DYN>>>(xh, w1h, b1, nullptr);

    dim3 g2(D_MODEL / BN, N_TOKENS / 128, N_EXPERTS);
    moe_gemm<D_FF, false><<<g2, 512, SMEM_DYN>>>(hh, w2h, b2, x);

    ln_kernel<<<N_TOKENS, 256>>>(gamma, beta, (float*)d_out);
}